// round 16
// baseline (speedup 1.0000x reference)
#include <cuda_runtime.h>
#include <cuda_fp16.h>
#include <math.h>
#include <stdint.h>

#define N_TOK 4096
#define TOTF  2048
#define HID   768
#define VOCABN 264

__device__ __align__(16) __half g_p0h[N_TOK * TOTF];
__device__ __align__(16) __half g_p1h[N_TOK * TOTF];
#define HWW (TOTF * 2 * TOTF)
#define PWW (TOTF * HID)
// w0/w1 stored column-INTERLEAVED: col 2j = nl_j, col 2j+1 = gate_j
__device__ __align__(16) __half g_w0i[HWW];
__device__ __align__(16) __half g_w1i[HWW];
__device__ __align__(16) __half g_pwh[PWW];
__device__ __align__(16) __half g_eh[VOCABN * 16];
#define WSP_TOT 197120
__device__ __align__(16) __half g_wsp[WSP_TOT];

// ---------------------------------------------------------------------------
__device__ __forceinline__ uint32_t smem_u32(const void* p) {
    uint32_t a;
    asm("{ .reg .u64 t; cvta.to.shared.u64 t, %1; cvt.u32.u64 %0, t; }"
        : "=r"(a) : "l"(p));
    return a;
}
#define STS128(addr, a, b, c, d) \
    asm volatile("st.shared.v4.b32 [%0], {%1,%2,%3,%4};" \
                 :: "r"(addr), "r"(a), "r"(b), "r"(c), "r"(d) : "memory")
#define CPASYNC16(dst, src) \
    asm volatile("cp.async.cg.shared.global [%0], [%1], 16;" \
                 :: "r"(dst), "l"(src) : "memory")
#define CPCOMMIT() asm volatile("cp.async.commit_group;" ::: "memory")
#define CPWAIT0()  asm volatile("cp.async.wait_group 0;" ::: "memory")
#define CPWAIT1()  asm volatile("cp.async.wait_group 1;" ::: "memory")

__device__ __forceinline__ void ldsm4(uint32_t a, uint32_t* r) {
    asm volatile("ldmatrix.sync.aligned.m8n8.x4.shared.b16 {%0,%1,%2,%3}, [%4];"
                 : "=r"(r[0]), "=r"(r[1]), "=r"(r[2]), "=r"(r[3]) : "r"(a));
}
__device__ __forceinline__ void ldsm4t(uint32_t a, uint32_t* r) {
    asm volatile("ldmatrix.sync.aligned.m8n8.x4.trans.shared.b16 {%0,%1,%2,%3}, [%4];"
                 : "=r"(r[0]), "=r"(r[1]), "=r"(r[2]), "=r"(r[3]) : "r"(a));
}
__device__ __forceinline__ void mma_fp(float* c, const uint32_t* a, const uint32_t* b) {
    asm volatile("mma.sync.aligned.m16n8k16.row.col.f32.f16.f16.f32 "
                 "{%0,%1,%2,%3}, {%4,%5,%6,%7}, {%8,%9}, {%0,%1,%2,%3};"
                 : "+f"(c[0]), "+f"(c[1]), "+f"(c[2]), "+f"(c[3])
                 : "r"(a[0]), "r"(a[1]), "r"(a[2]), "r"(a[3]), "r"(b[0]), "r"(b[1]));
}

// ===========================================================================
// Merged prep (one launch). Highway weights written interleaved.
// ===========================================================================
#define BIGN 4587520
__global__ void prep_all_kernel(const float* __restrict__ w0,
                                const float* __restrict__ w1,
                                const float* __restrict__ pw,
                                const float* __restrict__ c0, const float* __restrict__ c1,
                                const float* __restrict__ c2, const float* __restrict__ c3,
                                const float* __restrict__ c4, const float* __restrict__ c5,
                                const float* __restrict__ c6,
                                const float* __restrict__ emb) {
    size_t t = (size_t)blockIdx.x * 256 + threadIdx.x;
    if (t < BIGN) {
        size_t d4 = t * 4;
        if (d4 < 2 * HWW) {
            const float* src = (d4 < HWW) ? w0 : w1;
            __half* dh = (d4 < HWW) ? g_w0i : g_w1i;
            size_t off = (d4 < HWW) ? d4 : d4 - HWW;
            size_t k  = off >> 12;        // row (4096 interleaved cols)
            size_t dc = off & 4095;       // even
            size_t j0 = dc >> 1;
            float2 vn = *(const float2*)(src + k * 4096 + j0);
            float2 vg = *(const float2*)(src + k * 4096 + TOTF + j0);
            *(half2*)(dh + off)     = __halves2half2(__float2half_rn(vn.x), __float2half_rn(vg.x));
            *(half2*)(dh + off + 2) = __halves2half2(__float2half_rn(vn.y), __float2half_rn(vg.y));
        } else {
            size_t off = d4 - 2 * HWW;
            float4 v = *(const float4*)(pw + off);
            *(half2*)(g_pwh + off)     = __halves2half2(__float2half_rn(v.x), __float2half_rn(v.y));
            *(half2*)(g_pwh + off + 2) = __halves2half2(__float2half_rn(v.z), __float2half_rn(v.w));
        }
        return;
    }
    size_t u = t - BIGN;
    if (u < WSP_TOT) {
        int i = (int)u;
        const float* cw; int base, NF, W;
        if      (i <   512) { cw = c0; base = 0;     NF =   32; W = 1; }
        else if (i <  1536) { cw = c1; base = 512;   NF =   32; W = 2; }
        else if (i <  4608) { cw = c2; base = 1536;  NF =   64; W = 3; }
        else if (i < 12800) { cw = c3; base = 4608;  NF =  128; W = 4; }
        else if (i < 33280) { cw = c4; base = 12800; NF =  256; W = 5; }
        else if (i < 82432) { cw = c5; base = 33280; NF =  512; W = 6; }
        else                { cw = c6; base = 82432; NF = 1024; W = 7; }
        int local = i - base;
        int row = local / NF, f = local - row * NF;
        int c = row & 15, k = row >> 4;
        g_wsp[i] = __float2half_rn(cw[(f * 16 + c) * W + k]);
        return;
    }
    u -= WSP_TOT;
    if (u < VOCABN * 16) g_eh[u] = __float2half_rn(emb[u]);
}

// ===========================================================================
// Templated HMMA conv (w=3..7, single-term fp16): NT tiles/block (round 11)
// ===========================================================================
#define CX_W  21504u

template<int W, int NF, int NT>
__global__ __launch_bounds__(256)
void conv_mma_kernel(const int* __restrict__ ids, const float* __restrict__ cb,
                     int colBase, int wOff)
{
    constexpr int KD = 16 * W;
    constexpr int NPOS = 51 - W;
    extern __shared__ char smc[];
    const uint32_t sb = smem_u32(smc);
    const int tid = threadIdx.x;
    const int lane = tid & 31, wid = tid >> 5;
    const int n0 = blockIdx.x * 8;

    for (int t = tid; t < 448; t += 256) {
        int tok = t / 56, r = t - tok * 56;
        uint32_t dst = sb + (uint32_t)(tok * 2688 + r * 48);
        if (r < 50) {
            int id = ids[(n0 + tok) * 50 + r];
            const uint4* eh = (const uint4*)(g_eh + id * 16);
            uint4 h0 = eh[0], h1 = eh[1];
            STS128(dst,      h0.x, h0.y, h0.z, h0.w);
            STS128(dst + 16, h1.x, h1.y, h1.z, h1.w);
        } else {
            STS128(dst, 0u, 0u, 0u, 0u);
            STS128(dst + 16, 0u, 0u, 0u, 0u);
        }
    }

    const uint32_t xb = sb + (uint32_t)(wid * 2688 + (lane & 15) * 48 + (lane >> 4) * 16);
    const uint32_t bb = sb + CX_W + (uint32_t)((lane & 15) * 144 + (lane >> 4) * 16);

    #pragma unroll 1
    for (int ft = 0; ft < NT; ++ft) {
        const int f0 = (blockIdx.y * NT + ft) * 64;
        __syncthreads();
        for (int t = tid; t < KD * 8; t += 256) {
            int row = t >> 3, seg = t & 7;
            int gsrc = wOff + row * NF + f0 + seg * 8;
            uint4 h = *(const uint4*)(g_wsp + gsrc);
            uint32_t d = sb + CX_W + (uint32_t)(row * 144 + seg * 16);
            STS128(d, h.x, h.y, h.z, h.w);
        }
        __syncthreads();

        float C[3][8][4];
        #pragma unroll
        for (int mi = 0; mi < 3; mi++)
            #pragma unroll
            for (int nf = 0; nf < 8; nf++)
                #pragma unroll
                for (int q = 0; q < 4; q++) C[mi][nf][q] = 0.f;

        #pragma unroll
        for (int k = 0; k < W; ++k) {
            uint32_t ah[3][4];
            #pragma unroll
            for (int mi = 0; mi < 3; mi++)
                ldsm4(xb + (uint32_t)((mi * 16 + k) * 48), ah[mi]);
            uint32_t bf[8][2];
            #pragma unroll
            for (int ng = 0; ng < 4; ng++) {
                uint32_t t4[4];
                ldsm4t(bb + (uint32_t)(k * 16 * 144 + ng * 32), t4);
                bf[2*ng][0] = t4[0]; bf[2*ng][1] = t4[1];
                bf[2*ng+1][0] = t4[2]; bf[2*ng+1][1] = t4[3];
            }
            #pragma unroll
            for (int mi = 0; mi < 3; mi++)
                #pragma unroll
                for (int nf = 0; nf < 8; nf++)
                    mma_fp(C[mi][nf], ah[mi], bf[nf]);
        }

        float m0[8], m1[8];
        #pragma unroll
        for (int nf = 0; nf < 8; nf++) { m0[nf] = -1e30f; m1[nf] = -1e30f; }
        const int r0 = lane >> 2;
        #pragma unroll
        for (int mi = 0; mi < 3; mi++) {
            bool v0 = (mi * 16 + r0) < NPOS;
            bool v1 = (mi * 16 + r0 + 8) < NPOS;
            #pragma unroll
            for (int nf = 0; nf < 8; nf++) {
                if (v0) { m0[nf] = fmaxf(m0[nf], C[mi][nf][0]);
                          m1[nf] = fmaxf(m1[nf], C[mi][nf][1]); }
                if (v1) { m0[nf] = fmaxf(m0[nf], C[mi][nf][2]);
                          m1[nf] = fmaxf(m1[nf], C[mi][nf][3]); }
            }
        }
        #pragma unroll
        for (int nf = 0; nf < 8; nf++) {
            #pragma unroll
            for (int off = 4; off < 32; off <<= 1) {
                m0[nf] = fmaxf(m0[nf], __shfl_xor_sync(0xffffffffu, m0[nf], off));
                m1[nf] = fmaxf(m1[nf], __shfl_xor_sync(0xffffffffu, m1[nf], off));
            }
        }
        if (lane < 4) {
            const size_t base = (size_t)(n0 + wid) * TOTF + colBase + f0;
            #pragma unroll
            for (int nf = 0; nf < 8; nf++) {
                int fl = nf * 8 + lane * 2;
                float ox = fmaxf(m0[nf] + cb[f0 + fl], 0.f);
                float oy = fmaxf(m1[nf] + cb[f0 + fl + 1], 0.f);
                *(__half2*)(g_p0h + base + fl) =
                    __halves2half2(__float2half_rn(ox), __float2half_rn(oy));
            }
        }
    }
}

// ===========================================================================
// Merged w1+w2 HMMA conv (unchanged)
// ===========================================================================
#define M_XW  27648u
#define M_SMEM (27648 + 32 * 144)

__global__ __launch_bounds__(256)
void conv_w12_kernel(const int* __restrict__ ids,
                     const float* __restrict__ cb1, const float* __restrict__ cb2)
{
    extern __shared__ char smc[];
    const uint32_t sb = smem_u32(smc);
    const int tid = threadIdx.x;
    const int lane = tid & 31, wid = tid >> 5;
    const int n0 = blockIdx.x * 8;

    for (int t = tid; t < 576; t += 256) {
        int tok = t / 72, r = t - tok * 72;
        uint32_t dst = sb + (uint32_t)(tok * 3456 + r * 48);
        if (r < 50) {
            int id = ids[(n0 + tok) * 50 + r];
            const uint4* eh = (const uint4*)(g_eh + id * 16);
            uint4 h0 = eh[0], h1 = eh[1];
            STS128(dst,      h0.x, h0.y, h0.z, h0.w);
            STS128(dst + 16, h1.x, h1.y, h1.z, h1.w);
        } else {
            STS128(dst, 0u, 0u, 0u, 0u);
            STS128(dst + 16, 0u, 0u, 0u, 0u);
        }
    }
    {
        int t = tid;
        int row = t >> 3, seg = t & 7;
        uint32_t d = sb + M_XW + (uint32_t)(row * 144 + seg * 16);
        if (seg < 4) {
            if (row < 16) {
                uint4 h = *(const uint4*)(g_wsp + 0 + row * 32 + seg * 8);
                STS128(d, h.x, h.y, h.z, h.w);
            } else {
                STS128(d, 0u, 0u, 0u, 0u);
            }
        } else {
            uint4 h = *(const uint4*)(g_wsp + 512 + row * 32 + (seg - 4) * 8);
            STS128(d, h.x, h.y, h.z, h.w);
        }
    }
    __syncthreads();

    const uint32_t xb = sb + (uint32_t)(wid * 3456 + (lane & 15) * 48 + (lane >> 4) * 16);
    const uint32_t bb = sb + M_XW + (uint32_t)((lane & 15) * 144 + (lane >> 4) * 16);

    float C[4][8][4];
    #pragma unroll
    for (int mi = 0; mi < 4; mi++)
        #pragma unroll
        for (int nf = 0; nf < 8; nf++)
            #pragma unroll
            for (int q = 0; q < 4; q++) C[mi][nf][q] = 0.f;

    #pragma unroll
    for (int k = 0; k < 2; ++k) {
        uint32_t ah[4][4];
        #pragma unroll
        for (int mi = 0; mi < 4; mi++)
            ldsm4(xb + (uint32_t)((mi * 16 + k) * 48), ah[mi]);
        uint32_t bf[8][2];
        #pragma unroll
        for (int ng = 0; ng < 4; ng++) {
            uint32_t t4[4];
            ldsm4t(bb + (uint32_t)(k * 16 * 144 + ng * 32), t4);
            bf[2*ng][0] = t4[0]; bf[2*ng][1] = t4[1];
            bf[2*ng+1][0] = t4[2]; bf[2*ng+1][1] = t4[3];
        }
        #pragma unroll
        for (int mi = 0; mi < 4; mi++)
            #pragma unroll
            for (int nf = 0; nf < 8; nf++)
                mma_fp(C[mi][nf], ah[mi], bf[nf]);
    }

    float m0[8], m1[8];
    #pragma unroll
    for (int nf = 0; nf < 8; nf++) { m0[nf] = -1e30f; m1[nf] = -1e30f; }
    const int r0 = lane >> 2;
    #pragma unroll
    for (int mi = 0; mi < 4; mi++) {
        #pragma unroll
        for (int nf = 0; nf < 8; nf++) {
            int lim = (nf < 4) ? 50 : 49;
            bool v0 = (mi * 16 + r0) < lim;
            bool v1 = (mi * 16 + r0 + 8) < lim;
            if (v0) { m0[nf] = fmaxf(m0[nf], C[mi][nf][0]);
                      m1[nf] = fmaxf(m1[nf], C[mi][nf][1]); }
            if (v1) { m0[nf] = fmaxf(m0[nf], C[mi][nf][2]);
                      m1[nf] = fmaxf(m1[nf], C[mi][nf][3]); }
        }
    }
    #pragma unroll
    for (int nf = 0; nf < 8; nf++) {
        #pragma unroll
        for (int off = 4; off < 32; off <<= 1) {
            m0[nf] = fmaxf(m0[nf], __shfl_xor_sync(0xffffffffu, m0[nf], off));
            m1[nf] = fmaxf(m1[nf], __shfl_xor_sync(0xffffffffu, m1[nf], off));
        }
    }
    if (lane < 4) {
        const size_t base = (size_t)(n0 + wid) * TOTF;
        #pragma unroll
        for (int nf = 0; nf < 8; nf++) {
            int fl = nf * 8 + lane * 2;
            float b0 = (fl < 32) ? cb1[fl] : cb2[fl - 32];
            float b1 = (fl < 32) ? cb1[fl + 1] : cb2[fl - 31];
            float ox = fmaxf(m0[nf] + b0, 0.f);
            float oy = fmaxf(m1[nf] + b1, 0.f);
            *(__half2*)(g_p0h + base + fl) =
                __halves2half2(__float2half_rn(ox), __float2half_rn(oy));
        }
    }
}

// ===========================================================================
// fp16 GEMM, K-chunk 64, 3-stage cp.async, in-register epilogue.
//   HW : B = interleaved plane (nl,gate adjacent cols) -> fragment-local gating
//   !HW: proj, direct float2 stores + bias
// ===========================================================================
#define ASTRIDE 72
#define BSTRIDE 136
#define OFF_B   18432
#define BUFB    35840
#define GEMM_SMEM (3 * BUFB)

template<bool HW>
__global__ __launch_bounds__(256, 2)
void gemm_kernel(const __half* __restrict__ Ah,
                 const __half* __restrict__ Bh,
                 const float* __restrict__ bias,
                 float* __restrict__ outp,
                 __half* __restrict__ OutH)
{
    extern __shared__ char smg[];
    const uint32_t sb = smem_u32(smg);
    const int tid  = threadIdx.x;
    const int lane = tid & 31, wid = tid >> 5;
    const int wm = wid >> 2, wn = wid & 3;
    const int m0 = blockIdx.y * 128;
    const int bx = blockIdx.x;
    const int LDWB = HW ? (2 * TOTF) : HID;

    // B staging: unified contiguous 128-col tile (interleaved for HW)
    const int brow = tid >> 2;
    const int bs0  = (tid & 3) * 2;
    const int ar0 = tid >> 1;
    const int as0 = (tid & 1) * 4;

    auto STAGE = [&](int b, int k0) {
        const uint32_t base = sb + (uint32_t)b * BUFB;
        {
            const size_t arow_off = (size_t)(m0 + ar0) * TOTF + k0;
            uint32_t d = base + (uint32_t)(ar0 * ASTRIDE * 2);
            #pragma unroll
            for (int s = 0; s < 4; ++s) {
                int seg = as0 + s;
                CPASYNC16(d + seg * 16, (const void*)(Ah + arow_off + seg * 8));
            }
        }
        {
            #pragma unroll
            for (int s = 0; s < 2; ++s) {
                int seg = bs0 + s;
                const size_t bsrc = (size_t)(k0 + brow) * LDWB + bx * 128 + seg * 16;
                uint32_t d = base + OFF_B + (uint32_t)(brow * BSTRIDE * 2 + seg * 32);
                CPASYNC16(d,      (const void*)(Bh + bsrc));
                CPASYNC16(d + 16, (const void*)(Bh + bsrc + 8));
            }
        }
    };

    float C[4][4][4];
    #pragma unroll
    for (int mi = 0; mi < 4; mi++)
        #pragma unroll
        for (int ni = 0; ni < 4; ni++)
            #pragma unroll
            for (int q = 0; q < 4; q++) C[mi][ni][q] = 0.f;

    const uint32_t a_ln = (uint32_t)(((wm * 64 + (lane & 15)) * ASTRIDE + (lane >> 4) * 8) * 2);
    const uint32_t b_ln = (uint32_t)(((lane & 15) * BSTRIDE + wn * 32 + (lane >> 4) * 8) * 2);

    STAGE(0, 0);
    CPCOMMIT();
    STAGE(1, 64);
    CPCOMMIT();

    const int NCH = TOTF / 64;
    int bufi = 0;
    for (int ci = 0; ci < NCH; ++ci) {
        if (ci + 1 < NCH) CPWAIT1(); else CPWAIT0();
        __syncthreads();
        if (ci + 2 < NCH) {
            int nb = bufi + 2; if (nb >= 3) nb -= 3;
            STAGE(nb, (ci + 2) * 64);
            CPCOMMIT();
        }

        const uint32_t base = sb + (uint32_t)bufi * BUFB;
        #pragma unroll
        for (int ks = 0; ks < 4; ++ks) {
            uint32_t ah[4][4], bf[4][2];
            const uint32_t aad = base + a_ln + (uint32_t)(ks * 32);
            #pragma unroll
            for (int mi = 0; mi < 4; mi++)
                ldsm4(aad + mi * (16 * ASTRIDE * 2), ah[mi]);
            const uint32_t bad = base + OFF_B + b_ln + (uint32_t)(ks * 16 * BSTRIDE * 2);
            #pragma unroll
            for (int ng = 0; ng < 2; ng++) {
                uint32_t t[4];
                ldsm4t(bad + ng * 32, t);
                bf[2 * ng][0] = t[0]; bf[2 * ng][1] = t[1];
                bf[2 * ng + 1][0] = t[2]; bf[2 * ng + 1][1] = t[3];
            }
            #pragma unroll
            for (int mi = 0; mi < 4; mi++)
                #pragma unroll
                for (int ni = 0; ni < 4; ni++)
                    mma_fp(C[mi][ni], ah[mi], bf[ni]);
        }
        __syncthreads();
        if (++bufi == 3) bufi = 0;
    }

    // ---- in-register epilogue ----
    const int rbase = m0 + wm * 64 + (lane >> 2);
    if (HW) {
        #pragma unroll
        for (int ni = 0; ni < 4; ni++) {
            const int coln = wn * 32 + (lane & 3) * 2 + ni * 8;   // even
            const int j = bx * 64 + (coln >> 1);
            const float bn = bias[j];
            const float bg = bias[TOTF + j];
            #pragma unroll
            for (int mi = 0; mi < 4; mi++) {
                #pragma unroll
                for (int h = 0; h < 2; h++) {
                    const int r = rbase + mi * 16 + h * 8;
                    float nl = fmaxf(C[mi][ni][2 * h] + bn, 0.f);
                    float gv = C[mi][ni][2 * h + 1] + bg;
                    float g  = 1.f / (1.f + __expf(-gv));
                    size_t o = (size_t)r * TOTF + j;
                    float tv = __half2float(Ah[o]);
                    OutH[o] = __float2half_rn(g * tv + (1.f - g) * nl);
                }
            }
        }
    } else {
        #pragma unroll
        for (int ni = 0; ni < 4; ni++) {
            const int col = bx * 128 + wn * 32 + (lane & 3) * 2 + ni * 8;
            const float b0 = bias[col];
            const float b1 = bias[col + 1];
            #pragma unroll
            for (int mi = 0; mi < 4; mi++) {
                #pragma unroll
                for (int h = 0; h < 2; h++) {
                    const int r = rbase + mi * 16 + h * 8;
                    float2 v;
                    v.x = C[mi][ni][2 * h] + b0;
                    v.y = C[mi][ni][2 * h + 1] + b1;
                    *(float2*)&outp[(size_t)r * HID + col] = v;
                }
            }
        }
    }
}

// ---------------------------------------------------------------------------
template<int W, int NF, int NT>
static void launch_conv_mma(const int* ids, const float* cb, int colBase, int wOff)
{
    size_t smem = CX_W + (size_t)(16 * W) * 144;
    cudaFuncSetAttribute(conv_mma_kernel<W, NF, NT>,
                         cudaFuncAttributeMaxDynamicSharedMemorySize, (int)smem);
    conv_mma_kernel<W, NF, NT>
        <<<dim3(N_TOK / 8, NF / 64 / NT), 256, smem>>>(ids, cb, colBase, wOff);
}

extern "C" void kernel_launch(void* const* d_in, const int* in_sizes, int n_in,
                              void* d_out, int out_size)
{
    const int*   ids = (const int*)  d_in[0];
    const float* emb = (const float*)d_in[1];
    const float* cw[7]; const float* cb[7];
    for (int i = 0; i < 7; i++) {
        cw[i] = (const float*)d_in[2 + 2 * i];
        cb[i] = (const float*)d_in[3 + 2 * i];
    }
    const float* hw_w0 = (const float*)d_in[16];
    const float* hw_b0 = (const float*)d_in[17];
    const float* hw_w1 = (const float*)d_in[18];
    const float* hw_b1 = (const float*)d_in[19];
    const float* pw    = (const float*)d_in[20];
    const float* pb    = (const float*)d_in[21];
    float* out = (float*)d_out;

    __half *p0h, *p1h, *w0i, *w1i, *pwh;
    cudaGetSymbolAddress((void**)&p0h, g_p0h);
    cudaGetSymbolAddress((void**)&p1h, g_p1h);
    cudaGetSymbolAddress((void**)&w0i, g_w0i);
    cudaGetSymbolAddress((void**)&w1i, g_w1i);
    cudaGetSymbolAddress((void**)&pwh, g_pwh);

    {
        size_t tot = (size_t)BIGN + WSP_TOT + VOCABN * 16;
        int blocks = (int)((tot + 255) / 256);
        prep_all_kernel<<<blocks, 256>>>(hw_w0, hw_w1, pw,
                                         cw[0], cw[1], cw[2], cw[3], cw[4], cw[5], cw[6],
                                         emb);
    }

    cudaFuncSetAttribute(conv_w12_kernel,
                         cudaFuncAttributeMaxDynamicSharedMemorySize, M_SMEM);
    conv_w12_kernel<<<N_TOK / 8, 256, M_SMEM>>>(ids, cb[0], cb[1]);

    launch_conv_mma<3,   64, 1>(ids, cb[2],   64,  1536);
    launch_conv_mma<4,  128, 2>(ids, cb[3],  128,  4608);
    launch_conv_mma<5,  256, 2>(ids, cb[4],  256, 12800);
    launch_conv_mma<6,  512, 2>(ids, cb[5],  512, 33280);
    launch_conv_mma<7, 1024, 2>(ids, cb[6], 1024, 82432);

    cudaFuncSetAttribute(gemm_kernel<true>,
                         cudaFuncAttributeMaxDynamicSharedMemorySize, GEMM_SMEM);
    cudaFuncSetAttribute(gemm_kernel<false>,
                         cudaFuncAttributeMaxDynamicSharedMemorySize, GEMM_SMEM);
    gemm_kernel<true><<<dim3(32, 32), 256, GEMM_SMEM>>>(p0h, w0i, hw_b0, nullptr, p1h);
    gemm_kernel<true><<<dim3(32, 32), 256, GEMM_SMEM>>>(p1h, w1i, hw_b1, nullptr, p0h);
    gemm_kernel<false><<<dim3(6, 32), 256, GEMM_SMEM>>>(p0h, pwh, pb, out, nullptr);
}

// round 17
// speedup vs baseline: 1.0468x; 1.0468x over previous
#include <cuda_runtime.h>
#include <cuda_fp16.h>
#include <math.h>
#include <stdint.h>

#define N_TOK 4096
#define TOTF  2048
#define HID   768
#define VOCABN 264

__device__ __align__(16) __half g_p0h[N_TOK * TOTF];
__device__ __align__(16) __half g_p1h[N_TOK * TOTF];
#define HWW (TOTF * 2 * TOTF)
#define PWW (TOTF * HID)
__device__ __align__(16) __half g_w0h[HWW];
__device__ __align__(16) __half g_w1h[HWW];
__device__ __align__(16) __half g_pwh[PWW];
__device__ __align__(16) __half g_eh[VOCABN * 16];
#define WSP_TOT 197120
__device__ __align__(16) __half g_wsp[WSP_TOT];

// ---------------------------------------------------------------------------
__device__ __forceinline__ uint32_t smem_u32(const void* p) {
    uint32_t a;
    asm("{ .reg .u64 t; cvta.to.shared.u64 t, %1; cvt.u32.u64 %0, t; }"
        : "=r"(a) : "l"(p));
    return a;
}
#define STS128(addr, a, b, c, d) \
    asm volatile("st.shared.v4.b32 [%0], {%1,%2,%3,%4};" \
                 :: "r"(addr), "r"(a), "r"(b), "r"(c), "r"(d) : "memory")
#define STS64F(addr, x, y) \
    asm volatile("st.shared.v2.f32 [%0], {%1,%2};" \
                 :: "r"(addr), "f"(x), "f"(y) : "memory")
#define CPASYNC16(dst, src) \
    asm volatile("cp.async.cg.shared.global [%0], [%1], 16;" \
                 :: "r"(dst), "l"(src) : "memory")
#define CPCOMMIT() asm volatile("cp.async.commit_group;" ::: "memory")
#define CPWAIT0()  asm volatile("cp.async.wait_group 0;" ::: "memory")
#define CPWAIT1()  asm volatile("cp.async.wait_group 1;" ::: "memory")

__device__ __forceinline__ void ldsm4(uint32_t a, uint32_t* r) {
    asm volatile("ldmatrix.sync.aligned.m8n8.x4.shared.b16 {%0,%1,%2,%3}, [%4];"
                 : "=r"(r[0]), "=r"(r[1]), "=r"(r[2]), "=r"(r[3]) : "r"(a));
}
__device__ __forceinline__ void ldsm4t(uint32_t a, uint32_t* r) {
    asm volatile("ldmatrix.sync.aligned.m8n8.x4.trans.shared.b16 {%0,%1,%2,%3}, [%4];"
                 : "=r"(r[0]), "=r"(r[1]), "=r"(r[2]), "=r"(r[3]) : "r"(a));
}
__device__ __forceinline__ void mma_fp(float* c, const uint32_t* a, const uint32_t* b) {
    asm volatile("mma.sync.aligned.m16n8k16.row.col.f32.f16.f16.f32 "
                 "{%0,%1,%2,%3}, {%4,%5,%6,%7}, {%8,%9}, {%0,%1,%2,%3};"
                 : "+f"(c[0]), "+f"(c[1]), "+f"(c[2]), "+f"(c[3])
                 : "r"(a[0]), "r"(a[1]), "r"(a[2]), "r"(a[3]), "r"(b[0]), "r"(b[1]));
}

// ===========================================================================
// Merged prep (one launch)
// ===========================================================================
#define BIGN 4587520
__global__ void prep_all_kernel(const float* __restrict__ w0,
                                const float* __restrict__ w1,
                                const float* __restrict__ pw,
                                const float* __restrict__ c0, const float* __restrict__ c1,
                                const float* __restrict__ c2, const float* __restrict__ c3,
                                const float* __restrict__ c4, const float* __restrict__ c5,
                                const float* __restrict__ c6,
                                const float* __restrict__ emb) {
    size_t t = (size_t)blockIdx.x * 256 + threadIdx.x;
    if (t < BIGN) {
        size_t i4 = t * 4;
        const float* src;
        __half* dh;
        size_t off;
        if (i4 < HWW)          { src = w0; dh = g_w0h; off = i4; }
        else if (i4 < 2 * HWW) { src = w1; dh = g_w1h; off = i4 - HWW; }
        else                   { src = pw; dh = g_pwh; off = i4 - 2 * HWW; }
        float4 v = *(const float4*)(src + off);
        *(half2*)(dh + off)     = __halves2half2(__float2half_rn(v.x), __float2half_rn(v.y));
        *(half2*)(dh + off + 2) = __halves2half2(__float2half_rn(v.z), __float2half_rn(v.w));
        return;
    }
    size_t u = t - BIGN;
    if (u < WSP_TOT) {
        int i = (int)u;
        const float* cw; int base, NF, W;
        if      (i <   512) { cw = c0; base = 0;     NF =   32; W = 1; }
        else if (i <  1536) { cw = c1; base = 512;   NF =   32; W = 2; }
        else if (i <  4608) { cw = c2; base = 1536;  NF =   64; W = 3; }
        else if (i < 12800) { cw = c3; base = 4608;  NF =  128; W = 4; }
        else if (i < 33280) { cw = c4; base = 12800; NF =  256; W = 5; }
        else if (i < 82432) { cw = c5; base = 33280; NF =  512; W = 6; }
        else                { cw = c6; base = 82432; NF = 1024; W = 7; }
        int local = i - base;
        int row = local / NF, f = local - row * NF;
        int c = row & 15, k = row >> 4;
        g_wsp[i] = __float2half_rn(cw[(f * 16 + c) * W + k]);
        return;
    }
    u -= WSP_TOT;
    if (u < VOCABN * 16) g_eh[u] = __float2half_rn(emb[u]);
}

// ===========================================================================
// Templated HMMA conv (w=3..7, single-term fp16): NT filter tiles/block
// ===========================================================================
#define CX_W  21504u      // 8 tok * 56 rows * 48B

template<int W, int NF, int NT>
__global__ __launch_bounds__(256)
void conv_mma_kernel(const int* __restrict__ ids, const float* __restrict__ cb,
                     int colBase, int wOff)
{
    constexpr int KD = 16 * W;
    constexpr int NPOS = 51 - W;
    extern __shared__ char smc[];
    const uint32_t sb = smem_u32(smc);
    const int tid = threadIdx.x;
    const int lane = tid & 31, wid = tid >> 5;
    const int n0 = blockIdx.x * 8;

    for (int t = tid; t < 448; t += 256) {
        int tok = t / 56, r = t - tok * 56;
        uint32_t dst = sb + (uint32_t)(tok * 2688 + r * 48);
        if (r < 50) {
            int id = ids[(n0 + tok) * 50 + r];
            const uint4* eh = (const uint4*)(g_eh + id * 16);
            uint4 h0 = eh[0], h1 = eh[1];
            STS128(dst,      h0.x, h0.y, h0.z, h0.w);
            STS128(dst + 16, h1.x, h1.y, h1.z, h1.w);
        } else {
            STS128(dst, 0u, 0u, 0u, 0u);
            STS128(dst + 16, 0u, 0u, 0u, 0u);
        }
    }

    const uint32_t xb = sb + (uint32_t)(wid * 2688 + (lane & 15) * 48 + (lane >> 4) * 16);
    const uint32_t bb = sb + CX_W + (uint32_t)((lane & 15) * 144 + (lane >> 4) * 16);

    #pragma unroll 1
    for (int ft = 0; ft < NT; ++ft) {
        const int f0 = (blockIdx.y * NT + ft) * 64;
        __syncthreads();
        for (int t = tid; t < KD * 8; t += 256) {
            int row = t >> 3, seg = t & 7;
            int gsrc = wOff + row * NF + f0 + seg * 8;
            uint4 h = *(const uint4*)(g_wsp + gsrc);
            uint32_t d = sb + CX_W + (uint32_t)(row * 144 + seg * 16);
            STS128(d, h.x, h.y, h.z, h.w);
        }
        __syncthreads();

        float C[3][8][4];
        #pragma unroll
        for (int mi = 0; mi < 3; mi++)
            #pragma unroll
            for (int nf = 0; nf < 8; nf++)
                #pragma unroll
                for (int q = 0; q < 4; q++) C[mi][nf][q] = 0.f;

        #pragma unroll
        for (int k = 0; k < W; ++k) {
            uint32_t ah[3][4];
            #pragma unroll
            for (int mi = 0; mi < 3; mi++)
                ldsm4(xb + (uint32_t)((mi * 16 + k) * 48), ah[mi]);
            uint32_t bf[8][2];
            #pragma unroll
            for (int ng = 0; ng < 4; ng++) {
                uint32_t t4[4];
                ldsm4t(bb + (uint32_t)(k * 16 * 144 + ng * 32), t4);
                bf[2*ng][0] = t4[0]; bf[2*ng][1] = t4[1];
                bf[2*ng+1][0] = t4[2]; bf[2*ng+1][1] = t4[3];
            }
            #pragma unroll
            for (int mi = 0; mi < 3; mi++)
                #pragma unroll
                for (int nf = 0; nf < 8; nf++)
                    mma_fp(C[mi][nf], ah[mi], bf[nf]);
        }

        float m0[8], m1[8];
        #pragma unroll
        for (int nf = 0; nf < 8; nf++) { m0[nf] = -1e30f; m1[nf] = -1e30f; }
        const int r0 = lane >> 2;
        #pragma unroll
        for (int mi = 0; mi < 3; mi++) {
            bool v0 = (mi * 16 + r0) < NPOS;
            bool v1 = (mi * 16 + r0 + 8) < NPOS;
            #pragma unroll
            for (int nf = 0; nf < 8; nf++) {
                if (v0) { m0[nf] = fmaxf(m0[nf], C[mi][nf][0]);
                          m1[nf] = fmaxf(m1[nf], C[mi][nf][1]); }
                if (v1) { m0[nf] = fmaxf(m0[nf], C[mi][nf][2]);
                          m1[nf] = fmaxf(m1[nf], C[mi][nf][3]); }
            }
        }
        #pragma unroll
        for (int nf = 0; nf < 8; nf++) {
            #pragma unroll
            for (int off = 4; off < 32; off <<= 1) {
                m0[nf] = fmaxf(m0[nf], __shfl_xor_sync(0xffffffffu, m0[nf], off));
                m1[nf] = fmaxf(m1[nf], __shfl_xor_sync(0xffffffffu, m1[nf], off));
            }
        }
        if (lane < 4) {
            const size_t base = (size_t)(n0 + wid) * TOTF + colBase + f0;
            #pragma unroll
            for (int nf = 0; nf < 8; nf++) {
                int fl = nf * 8 + lane * 2;
                float ox = fmaxf(m0[nf] + cb[f0 + fl], 0.f);
                float oy = fmaxf(m1[nf] + cb[f0 + fl + 1], 0.f);
                *(__half2*)(g_p0h + base + fl) =
                    __halves2half2(__float2half_rn(ox), __float2half_rn(oy));
            }
        }
    }
}

// ===========================================================================
// Merged w1+w2 HMMA conv
// ===========================================================================
#define M_XW  27648u
#define M_SMEM (27648 + 32 * 144)

__global__ __launch_bounds__(256)
void conv_w12_kernel(const int* __restrict__ ids,
                     const float* __restrict__ cb1, const float* __restrict__ cb2)
{
    extern __shared__ char smc[];
    const uint32_t sb = smem_u32(smc);
    const int tid = threadIdx.x;
    const int lane = tid & 31, wid = tid >> 5;
    const int n0 = blockIdx.x * 8;

    for (int t = tid; t < 576; t += 256) {
        int tok = t / 72, r = t - tok * 72;
        uint32_t dst = sb + (uint32_t)(tok * 3456 + r * 48);
        if (r < 50) {
            int id = ids[(n0 + tok) * 50 + r];
            const uint4* eh = (const uint4*)(g_eh + id * 16);
            uint4 h0 = eh[0], h1 = eh[1];
            STS128(dst,      h0.x, h0.y, h0.z, h0.w);
            STS128(dst + 16, h1.x, h1.y, h1.z, h1.w);
        } else {
            STS128(dst, 0u, 0u, 0u, 0u);
            STS128(dst + 16, 0u, 0u, 0u, 0u);
        }
    }
    {
        int t = tid;
        int row = t >> 3, seg = t & 7;
        uint32_t d = sb + M_XW + (uint32_t)(row * 144 + seg * 16);
        if (seg < 4) {
            if (row < 16) {
                uint4 h = *(const uint4*)(g_wsp + 0 + row * 32 + seg * 8);
                STS128(d, h.x, h.y, h.z, h.w);
            } else {
                STS128(d, 0u, 0u, 0u, 0u);
            }
        } else {
            uint4 h = *(const uint4*)(g_wsp + 512 + row * 32 + (seg - 4) * 8);
            STS128(d, h.x, h.y, h.z, h.w);
        }
    }
    __syncthreads();

    const uint32_t xb = sb + (uint32_t)(wid * 3456 + (lane & 15) * 48 + (lane >> 4) * 16);
    const uint32_t bb = sb + M_XW + (uint32_t)((lane & 15) * 144 + (lane >> 4) * 16);

    float C[4][8][4];
    #pragma unroll
    for (int mi = 0; mi < 4; mi++)
        #pragma unroll
        for (int nf = 0; nf < 8; nf++)
            #pragma unroll
            for (int q = 0; q < 4; q++) C[mi][nf][q] = 0.f;

    #pragma unroll
    for (int k = 0; k < 2; ++k) {
        uint32_t ah[4][4];
        #pragma unroll
        for (int mi = 0; mi < 4; mi++)
            ldsm4(xb + (uint32_t)((mi * 16 + k) * 48), ah[mi]);
        uint32_t bf[8][2];
        #pragma unroll
        for (int ng = 0; ng < 4; ng++) {
            uint32_t t4[4];
            ldsm4t(bb + (uint32_t)(k * 16 * 144 + ng * 32), t4);
            bf[2*ng][0] = t4[0]; bf[2*ng][1] = t4[1];
            bf[2*ng+1][0] = t4[2]; bf[2*ng+1][1] = t4[3];
        }
        #pragma unroll
        for (int mi = 0; mi < 4; mi++)
            #pragma unroll
            for (int nf = 0; nf < 8; nf++)
                mma_fp(C[mi][nf], ah[mi], bf[nf]);
    }

    float m0[8], m1[8];
    #pragma unroll
    for (int nf = 0; nf < 8; nf++) { m0[nf] = -1e30f; m1[nf] = -1e30f; }
    const int r0 = lane >> 2;
    #pragma unroll
    for (int mi = 0; mi < 4; mi++) {
        #pragma unroll
        for (int nf = 0; nf < 8; nf++) {
            int lim = (nf < 4) ? 50 : 49;
            bool v0 = (mi * 16 + r0) < lim;
            bool v1 = (mi * 16 + r0 + 8) < lim;
            if (v0) { m0[nf] = fmaxf(m0[nf], C[mi][nf][0]);
                      m1[nf] = fmaxf(m1[nf], C[mi][nf][1]); }
            if (v1) { m0[nf] = fmaxf(m0[nf], C[mi][nf][2]);
                      m1[nf] = fmaxf(m1[nf], C[mi][nf][3]); }
        }
    }
    #pragma unroll
    for (int nf = 0; nf < 8; nf++) {
        #pragma unroll
        for (int off = 4; off < 32; off <<= 1) {
            m0[nf] = fmaxf(m0[nf], __shfl_xor_sync(0xffffffffu, m0[nf], off));
            m1[nf] = fmaxf(m1[nf], __shfl_xor_sync(0xffffffffu, m1[nf], off));
        }
    }
    if (lane < 4) {
        const size_t base = (size_t)(n0 + wid) * TOTF;
        #pragma unroll
        for (int nf = 0; nf < 8; nf++) {
            int fl = nf * 8 + lane * 2;
            float b0 = (fl < 32) ? cb1[fl] : cb2[fl - 32];
            float b1 = (fl < 32) ? cb1[fl + 1] : cb2[fl - 31];
            float ox = fmaxf(m0[nf] + b0, 0.f);
            float oy = fmaxf(m1[nf] + b1, 0.f);
            *(__half2*)(g_p0h + base + fl) =
                __halves2half2(__float2half_rn(ox), __float2half_rn(oy));
        }
    }
}

// ===========================================================================
// fp16 GEMM, K-chunk 64, 3-stage cp.async. ONE barrier per chunk (the
// bottom barrier is redundant with a 3-deep ring: the buffer staged at
// chunk ci was consumed at ci-1, already protected by ci's top barrier).
// ===========================================================================
#define ASTRIDE 72
#define BSTRIDE 136
#define OFF_B   18432
#define BUFB    35840
#define GEMM_SMEM (3 * BUFB)

template<bool HW>
__global__ __launch_bounds__(256, 2)
void gemm_kernel(const __half* __restrict__ Ah,
                 const __half* __restrict__ Bh,
                 const float* __restrict__ bias,
                 float* __restrict__ outp,
                 __half* __restrict__ OutH)
{
    extern __shared__ char smg[];
    const uint32_t sb = smem_u32(smg);
    const int tid  = threadIdx.x;
    const int lane = tid & 31, wid = tid >> 5;
    const int wm = wid >> 2, wn = wid & 3;
    const int m0 = blockIdx.y * 128;
    const int bx = blockIdx.x;
    const int LDWB = HW ? (2 * TOTF) : HID;

    const int brow = tid >> 2;
    const int bs0  = (tid & 3) * 2;
    int bcolv[2];
    #pragma unroll
    for (int s = 0; s < 2; ++s) {
        int seg = bs0 + s;
        if (HW) bcolv[s] = (seg < 4) ? bx * 64 + seg * 16 : TOTF + bx * 64 + (seg - 4) * 16;
        else    bcolv[s] = bx * 128 + seg * 16;
    }
    const int ar0 = tid >> 1;
    const int as0 = (tid & 1) * 4;

    auto STAGE = [&](int b, int k0) {
        const uint32_t base = sb + (uint32_t)b * BUFB;
        {
            const size_t arow_off = (size_t)(m0 + ar0) * TOTF + k0;
            uint32_t d = base + (uint32_t)(ar0 * ASTRIDE * 2);
            #pragma unroll
            for (int s = 0; s < 4; ++s) {
                int seg = as0 + s;
                CPASYNC16(d + seg * 16, (const void*)(Ah + arow_off + seg * 8));
            }
        }
        {
            #pragma unroll
            for (int s = 0; s < 2; ++s) {
                int seg = bs0 + s;
                const size_t bsrc = (size_t)(k0 + brow) * LDWB + bcolv[s];
                uint32_t d = base + OFF_B + (uint32_t)(brow * BSTRIDE * 2 + seg * 32);
                CPASYNC16(d,      (const void*)(Bh + bsrc));
                CPASYNC16(d + 16, (const void*)(Bh + bsrc + 8));
            }
        }
    };

    float C[4][4][4];
    #pragma unroll
    for (int mi = 0; mi < 4; mi++)
        #pragma unroll
        for (int ni = 0; ni < 4; ni++)
            #pragma unroll
            for (int q = 0; q < 4; q++) C[mi][ni][q] = 0.f;

    const uint32_t a_ln = (uint32_t)(((wm * 64 + (lane & 15)) * ASTRIDE + (lane >> 4) * 8) * 2);
    const uint32_t b_ln = (uint32_t)(((lane & 15) * BSTRIDE + wn * 32 + (lane >> 4) * 8) * 2);

    STAGE(0, 0);
    CPCOMMIT();
    STAGE(1, 64);
    CPCOMMIT();

    const int NCH = TOTF / 64;
    int bufi = 0;
    for (int ci = 0; ci < NCH; ++ci) {
        if (ci + 1 < NCH) CPWAIT1(); else CPWAIT0();
        __syncthreads();                       // single barrier per chunk
        if (ci + 2 < NCH) {
            int nb = bufi + 2; if (nb >= 3) nb -= 3;
            STAGE(nb, (ci + 2) * 64);
            CPCOMMIT();
        }

        const uint32_t base = sb + (uint32_t)bufi * BUFB;
        #pragma unroll
        for (int ks = 0; ks < 4; ++ks) {
            uint32_t ah[4][4], bf[4][2];
            const uint32_t aad = base + a_ln + (uint32_t)(ks * 32);
            #pragma unroll
            for (int mi = 0; mi < 4; mi++)
                ldsm4(aad + mi * (16 * ASTRIDE * 2), ah[mi]);
            const uint32_t bad = base + OFF_B + b_ln + (uint32_t)(ks * 16 * BSTRIDE * 2);
            #pragma unroll
            for (int ng = 0; ng < 2; ng++) {
                uint32_t t[4];
                ldsm4t(bad + ng * 32, t);
                bf[2 * ng][0] = t[0]; bf[2 * ng][1] = t[1];
                bf[2 * ng + 1][0] = t[2]; bf[2 * ng + 1][1] = t[3];
            }
            #pragma unroll
            for (int mi = 0; mi < 4; mi++)
                #pragma unroll
                for (int ni = 0; ni < 4; ni++)
                    mma_fp(C[mi][ni], ah[mi], bf[ni]);
        }
        if (++bufi == 3) bufi = 0;
    }
    __syncthreads();   // all mainloop smem reads done before Cs overwrites

    const int crow  = wm * 64 + (lane >> 2);
    const int ccol0 = wn * 32 + (lane & 3) * 2;
    #pragma unroll
    for (int mi = 0; mi < 4; mi++)
        #pragma unroll
        for (int ni = 0; ni < 4; ni++) {
            uint32_t o0 = sb + (uint32_t)(((crow + mi * 16) * 132 + ccol0 + ni * 8) * 4);
            STS64F(o0, C[mi][ni][0], C[mi][ni][1]);
            STS64F(o0 + (uint32_t)(8 * 132 * 4), C[mi][ni][2], C[mi][ni][3]);
        }
    __syncthreads();

    const float* Cs = (const float*)smg;
    if (HW) {
        const int j0h = bx * 64;
        #pragma unroll 4
        for (int t = 0; t < 32; ++t) {
            int idx = t * 256 + tid;
            int m = idx >> 6, u = idx & 63;
            float nl = fmaxf(Cs[m * 132 + u] + bias[j0h + u], 0.f);
            float gv = Cs[m * 132 + 64 + u] + bias[TOTF + j0h + u];
            float g  = 1.f / (1.f + __expf(-gv));
            size_t o = (size_t)(m0 + m) * TOTF + j0h + u;
            float tv = __half2float(Ah[o]);
            float vo = g * tv + (1.f - g) * nl;
            OutH[o] = __float2half_rn(vo);
        }
    } else {
        const int j0 = bx * 128;
        #pragma unroll 4
        for (int t = 0; t < 64; ++t) {
            int idx = t * 256 + tid;
            int m = idx >> 7, n = idx & 127;
            outp[(size_t)(m0 + m) * HID + j0 + n] = Cs[m * 132 + n] + bias[j0 + n];
        }
    }
}

// ---------------------------------------------------------------------------
template<int W, int NF, int NT>
static void launch_conv_mma(const int* ids, const float* cb, int colBase, int wOff)
{
    size_t smem = CX_W + (size_t)(16 * W) * 144;
    cudaFuncSetAttribute(conv_mma_kernel<W, NF, NT>,
                         cudaFuncAttributeMaxDynamicSharedMemorySize, (int)smem);
    conv_mma_kernel<W, NF, NT>
        <<<dim3(N_TOK / 8, NF / 64 / NT), 256, smem>>>(ids, cb, colBase, wOff);
}

extern "C" void kernel_launch(void* const* d_in, const int* in_sizes, int n_in,
                              void* d_out, int out_size)
{
    const int*   ids = (const int*)  d_in[0];
    const float* emb = (const float*)d_in[1];
    const float* cw[7]; const float* cb[7];
    for (int i = 0; i < 7; i++) {
        cw[i] = (const float*)d_in[2 + 2 * i];
        cb[i] = (const float*)d_in[3 + 2 * i];
    }
    const float* hw_w0 = (const float*)d_in[16];
    const float* hw_b0 = (const float*)d_in[17];
    const float* hw_w1 = (const float*)d_in[18];
    const float* hw_b1 = (const float*)d_in[19];
    const float* pw    = (const float*)d_in[20];
    const float* pb    = (const float*)d_in[21];
    float* out = (float*)d_out;

    __half *p0h, *p1h, *w0h, *w1h, *pwh;
    cudaGetSymbolAddress((void**)&p0h, g_p0h);
    cudaGetSymbolAddress((void**)&p1h, g_p1h);
    cudaGetSymbolAddress((void**)&w0h, g_w0h);
    cudaGetSymbolAddress((void**)&w1h, g_w1h);
    cudaGetSymbolAddress((void**)&pwh, g_pwh);

    {
        size_t tot = (size_t)BIGN + WSP_TOT + VOCABN * 16;
        int blocks = (int)((tot + 255) / 256);
        prep_all_kernel<<<blocks, 256>>>(hw_w0, hw_w1, pw,
                                         cw[0], cw[1], cw[2], cw[3], cw[4], cw[5], cw[6],
                                         emb);
    }

    cudaFuncSetAttribute(conv_w12_kernel,
                         cudaFuncAttributeMaxDynamicSharedMemorySize, M_SMEM);
    conv_w12_kernel<<<N_TOK / 8, 256, M_SMEM>>>(ids, cb[0], cb[1]);

    launch_conv_mma<3,   64, 1>(ids, cb[2],   64,  1536);
    launch_conv_mma<4,  128, 2>(ids, cb[3],  128,  4608);
    launch_conv_mma<5,  256, 2>(ids, cb[4],  256, 12800);
    launch_conv_mma<6,  512, 2>(ids, cb[5],  512, 33280);
    launch_conv_mma<7, 1024, 2>(ids, cb[6], 1024, 82432);

    cudaFuncSetAttribute(gemm_kernel<true>,
                         cudaFuncAttributeMaxDynamicSharedMemorySize, GEMM_SMEM);
    cudaFuncSetAttribute(gemm_kernel<false>,
                         cudaFuncAttributeMaxDynamicSharedMemorySize, GEMM_SMEM);
    gemm_kernel<true><<<dim3(32, 32), 256, GEMM_SMEM>>>(p0h, w0h, hw_b0, nullptr, p1h);
    gemm_kernel<true><<<dim3(32, 32), 256, GEMM_SMEM>>>(p1h, w1h, hw_b1, nullptr, p0h);
    gemm_kernel<false><<<dim3(6, 32), 256, GEMM_SMEM>>>(p0h, pwh, pb, out, nullptr);
}